// round 7
// baseline (speedup 1.0000x reference)
#include <cuda_runtime.h>
#include <math.h>

// ---------------------------------------------------------------------------
// NCC3D: z[8,1,8,8,8], x[8,1,128,128,128] -> out[8,1,121,121,121]
//   k_template : zero-mean template + L2 norm
//   k_whsum    : fused W+H window sums of x, x^2 (smem-resident per (b,d) slice)
//   k_dsum2    : rolling D window sums + denominator inverse -> g_dinv
//   k_cross    : direct correlation, f32x2 packed FMA, swizzled conflict-free
//                smem tile; row-shared inner loop: each tile row loaded once
//                feeds BOTH h-phases (halves LDS -> FMA-pipe bound)
// ---------------------------------------------------------------------------

#define NB 8

__device__ float g_zc[NB * 512];
__device__ float g_zn[NB];
__device__ float g_t1[(size_t)NB * 128 * 121 * 121];
__device__ float g_t2[(size_t)NB * 128 * 121 * 121];
__device__ float g_dinv[(size_t)NB * 121 * 121 * 121];

// ---------------- packed f32x2 helpers ----------------
__device__ __forceinline__ void fma2(unsigned long long& a,
                                     unsigned long long x,
                                     unsigned long long z) {
    asm("fma.rn.f32x2 %0, %1, %2, %0;" : "+l"(a) : "l"(x), "l"(z));
}
__device__ __forceinline__ float2 u2f(unsigned long long u) {
    float2 f;
    asm("mov.b64 {%0, %1}, %2;" : "=f"(f.x), "=f"(f.y) : "l"(u));
    return f;
}

// ---------------- template stats ----------------
__global__ void ncc_k_template(const float* __restrict__ z) {
    __shared__ float red[512];
    int b = blockIdx.x, t = threadIdx.x;
    float v = z[b * 512 + t];
    red[t] = v;
    __syncthreads();
    for (int s = 256; s > 0; s >>= 1) {
        if (t < s) red[t] += red[t + s];
        __syncthreads();
    }
    float mean = red[0] * (1.0f / 512.0f);
    __syncthreads();
    float c = v - mean;
    g_zc[b * 512 + t] = c;
    red[t] = c * c;
    __syncthreads();
    for (int s = 256; s > 0; s >>= 1) {
        if (t < s) red[t] += red[t + s];
        __syncthreads();
    }
    if (t == 0) g_zn[b] = sqrtf(red[0]);
}

// ---------------- fused W + H window sums (one (b,d) slice per block) -------
#define WH_SMEM (3 * 16384 * 4)
__global__ void __launch_bounds__(256) ncc_k_whsum(const float* __restrict__ x) {
    extern __shared__ float sm[];
    float* xs = sm;              // [128][128]
    float* s1 = sm + 16384;      // [128][128] (w<121 valid)
    float* s2 = sm + 32768;
    int bd = blockIdx.x, tid = threadIdx.x;
    const float* xp = x + (size_t)bd * 16384;
    for (int i = tid; i < 16384; i += 256) xs[i] = xp[i];
    __syncthreads();
    for (int i = tid; i < 16384; i += 256) {
        int w = i & 127;
        if (w < 121) {
            float a = 0.f, c = 0.f;
#pragma unroll
            for (int k = 0; k < 8; k++) {
                float v = xs[i + k];
                a += v;
                c += v * v;
            }
            s1[i] = a;
            s2[i] = c;
        }
    }
    __syncthreads();
    for (int i = tid; i < 121 * 128; i += 256) {
        int ho = i >> 7, w = i & 127;
        if (w < 121) {
            float a = 0.f, c = 0.f;
#pragma unroll
            for (int k = 0; k < 8; k++) {
                a += s1[i + (k << 7)];
                c += s2[i + (k << 7)];
            }
            size_t o = ((size_t)bd * 121 + ho) * 121 + w;
            g_t1[o] = a;
            g_t2[o] = c;
        }
    }
}

// ---------------- rolling D sums + denominator inverse ----------------------
__global__ void __launch_bounds__(256) ncc_k_dsum2() {
    int p = blockIdx.x * 256 + threadIdx.x;
    if (p >= 14641) return;
    int h = p / 121, w = p - h * 121;
    int b = blockIdx.z;
    const int dst[5] = {0, 31, 61, 91, 121};
    int d0 = dst[blockIdx.y], d1 = dst[blockIdx.y + 1];
    size_t tbase = (((size_t)(b * 128)) * 121 + h) * 121 + w;
    float r1[8], r2[8], s1 = 0.f, s2 = 0.f;
#pragma unroll
    for (int k = 0; k < 8; k++) {
        float a = g_t1[tbase + (size_t)(d0 + k) * 14641];
        float c = g_t2[tbase + (size_t)(d0 + k) * 14641];
        r1[k] = a;
        r2[k] = c;
        s1 += a;
        s2 += c;
    }
    float zn = g_zn[b];
    size_t obase = (((size_t)(b * 121)) * 121 + h) * 121 + w;
    for (int dd = d0; dd < d1; dd += 8) {
#pragma unroll
        for (int j = 0; j < 8; j++) {
            int d = dd + j;
            if (d < d1) {
                float var = fmaxf(s2 - s1 * s1 * (1.0f / 512.0f), 0.0f);
                g_dinv[obase + (size_t)d * 14641] =
                    1.0f / (sqrtf(var + 1e-12f) * zn + 1e-5f);
                if (d + 1 < d1) {
                    float n1 = g_t1[tbase + (size_t)(d + 8) * 14641];
                    float n2 = g_t2[tbase + (size_t)(d + 8) * 14641];
                    s1 += n1 - r1[j];
                    r1[j] = n1;
                    s2 += n2 - r2[j];
                    r2[j] = n2;
                }
            }
        }
    }
}

// ---------------- cross-correlation (FMA-bound) -----------------------------
// Block 256 threads = 8 warps. Output tile: 8(d) x 8(h) x 128(w).
// Thread: 1 od, 2 oh (phases 0/1), 16 w. Accumulators: even bank A[8]
// (out pairs 2p,2p+1), odd bank B[9] (out pairs 2i-1,2i), per phase.
// Row-shared loop: tile row r (= oh0+r) is loaded ONCE and feeds
//   phase0 with z row r    (r = 0..7)
//   phase1 with z row r-1  (r = 1..8)
// Tile rows swizzled by 16B granule: phys = g ^ (g>>3) (involution),
// row stride 152 floats (38 granules, == 6 mod 8) -> conflict-free LDS.128.
#define CTH 15
#define RST 152
#define TILE_F (15 * 15 * 152)
#define CR_SMEM ((TILE_F + 1024) * 4)

__global__ void __launch_bounds__(256, 1) ncc_k_cross(const float* __restrict__ x,
                                                      float* __restrict__ out) {
    extern __shared__ float sm[];
    float* tile = sm;
    unsigned long long* zp = (unsigned long long*)(sm + TILE_F);

    int b = blockIdx.z;
    int d0 = blockIdx.x * 8, h0 = blockIdx.y * 8;
    int tid = threadIdx.x;

    const float* xb = x + (size_t)b * 2097152;
    for (int i = tid; i < TILE_F; i += 256) {
        int row = i / RST;
        int wp = i - row * RST;
        int lg = wp >> 2;
        lg = lg ^ (lg >> 3);                 // inverse == forward (involution)
        int w = (lg << 2) | (wp & 3);
        float v = 0.f;
        if (w < 128) {
            int dd = row / CTH, hh = row - dd * CTH;
            int gd = min(d0 + dd, 127), gh = min(h0 + hh, 127);
            v = xb[((size_t)(gd * 128 + gh)) * 128 + w];
        }
        tile[i] = v;
    }
    for (int t = tid; t < 512; t += 256) {
        float zv = g_zc[b * 512 + t];
        float2 f = make_float2(zv, zv);
        zp[t] = *(unsigned long long*)&f;
    }
    __syncthreads();

    int wt = tid & 7, c = tid >> 3;
    int od = c >> 2, oh0 = (c & 3) * 2;
    int wb = wt * 16;

    int off[6];
#pragma unroll
    for (int q = 0; q < 6; q++) {
        int g = 4 * wt + q;
        off[q] = (g ^ (g >> 3)) << 2;        // float offset of swizzled granule
    }

    unsigned long long A0[8], B0[9], A1[8], B1[9];
#pragma unroll
    for (int p = 0; p < 8; p++) { A0[p] = 0ull; A1[p] = 0ull; }
#pragma unroll
    for (int i2 = 0; i2 < 9; i2++) { B0[i2] = 0ull; B1[i2] = 0ull; }

#pragma unroll 1
    for (int kd = 0; kd < 8; kd++) {
        // base of tile row (od+kd, oh0): per-r offsets become LDS immediates
        const float* bp = tile + (od + kd) * (CTH * RST) + oh0 * RST;
        const unsigned long long* zkd = zp + (kd << 3) * 8;

        unsigned long long zbuf[2][8];       // alternating z-row buffers

#pragma unroll
        for (int r = 0; r < 9; r++) {
            // ---- load tile row r once (6 x LDS.128) ----
            unsigned long long pe[12];
#pragma unroll
            for (int q = 0; q < 6; q++) {
                ulonglong2 v = *(const ulonglong2*)(bp + r * RST + off[q]);
                pe[2 * q] = v.x;
                pe[2 * q + 1] = v.y;
            }
            // ---- load z row r (broadcast) into alternating buffer ----
            if (r < 8) {
                const ulonglong2* z2 = (const ulonglong2*)(zkd + r * 8);
                ulonglong2 za = z2[0], zb = z2[1], zc = z2[2], zd = z2[3];
                unsigned long long* zc_ = zbuf[r & 1];
                zc_[0] = za.x; zc_[1] = za.y; zc_[2] = zb.x; zc_[3] = zb.y;
                zc_[4] = zc.x; zc_[5] = zc.y; zc_[6] = zd.x; zc_[7] = zd.y;
            }
            // ---- phase0: output row oh0, tap kh = r ----
            if (r < 8) {
                const unsigned long long* zr = zbuf[r & 1];
#pragma unroll
                for (int m = 0; m < 4; m++) {
                    unsigned long long ze = zr[2 * m];
#pragma unroll
                    for (int p = 0; p < 8; p++) fma2(A0[p], pe[p + m], ze);
                }
#pragma unroll
                for (int m = 0; m < 4; m++) {
                    unsigned long long zo = zr[2 * m + 1];
#pragma unroll
                    for (int i2 = 0; i2 < 9; i2++) fma2(B0[i2], pe[i2 + m], zo);
                }
            }
            // ---- phase1: output row oh0+1, tap kh = r-1 ----
            if (r >= 1) {
                const unsigned long long* zr = zbuf[(r - 1) & 1];
#pragma unroll
                for (int m = 0; m < 4; m++) {
                    unsigned long long ze = zr[2 * m];
#pragma unroll
                    for (int p = 0; p < 8; p++) fma2(A1[p], pe[p + m], ze);
                }
#pragma unroll
                for (int m = 0; m < 4; m++) {
                    unsigned long long zo = zr[2 * m + 1];
#pragma unroll
                    for (int i2 = 0; i2 < 9; i2++) fma2(B1[i2], pe[i2 + m], zo);
                }
            }
        }
    }

    int d = d0 + od;
    if (d >= 121) return;
    size_t dbase_o = ((size_t)(b * 121 + d)) * 121;

    {
        int h = h0 + oh0;
        if (h < 121) {
            float res[16];
#pragma unroll
            for (int p = 0; p < 8; p++) {
                float2 a = u2f(A0[p]);
                float2 bl = u2f(B0[p]);
                float2 br = u2f(B0[p + 1]);
                res[2 * p] = a.x + bl.y;
                res[2 * p + 1] = a.y + br.x;
            }
            size_t base = (dbase_o + h) * 121;
#pragma unroll
            for (int j = 0; j < 16; j++) {
                int w = wb + j;
                if (w < 121) out[base + w] = res[j] * __ldg(&g_dinv[base + w]);
            }
        }
    }
    {
        int h = h0 + oh0 + 1;
        if (h < 121) {
            float res[16];
#pragma unroll
            for (int p = 0; p < 8; p++) {
                float2 a = u2f(A1[p]);
                float2 bl = u2f(B1[p]);
                float2 br = u2f(B1[p + 1]);
                res[2 * p] = a.x + bl.y;
                res[2 * p + 1] = a.y + br.x;
            }
            size_t base = (dbase_o + h) * 121;
#pragma unroll
            for (int j = 0; j < 16; j++) {
                int w = wb + j;
                if (w < 121) out[base + w] = res[j] * __ldg(&g_dinv[base + w]);
            }
        }
    }
}

// ---------------------------------------------------------------------------
extern "C" void kernel_launch(void* const* d_in, const int* in_sizes, int n_in,
                              void* d_out, int out_size) {
    (void)n_in;
    (void)out_size;
    const float* z = (const float*)d_in[0];
    const float* x = (const float*)d_in[1];
    if (in_sizes[0] != NB * 512) {
        z = (const float*)d_in[1];
        x = (const float*)d_in[0];
    }
    float* out = (float*)d_out;

    cudaFuncSetAttribute(ncc_k_whsum,
                         cudaFuncAttributeMaxDynamicSharedMemorySize, WH_SMEM);
    cudaFuncSetAttribute(ncc_k_cross,
                         cudaFuncAttributeMaxDynamicSharedMemorySize, CR_SMEM);

    ncc_k_template<<<NB, 512>>>(z);
    ncc_k_whsum<<<NB * 128, 256, WH_SMEM>>>(x);
    ncc_k_dsum2<<<dim3(58, 4, NB), 256>>>();
    ncc_k_cross<<<dim3(16, 16, NB), 256, CR_SMEM>>>(x, out);
}

// round 8
// speedup vs baseline: 1.1019x; 1.1019x over previous
#include <cuda_runtime.h>
#include <math.h>

// ---------------------------------------------------------------------------
// NCC3D: z[8,1,8,8,8], x[8,1,128,128,128] -> out[8,1,121,121,121]
//   k_template : zero-mean template + L2 norm
//   k_whsum    : fused W+H window sums of x, x^2 (smem-resident per (b,d) slice)
//   k_dsum2    : rolling D window sums + denominator inverse -> g_dinv
//   k_cross    : direct correlation, f32x2 packed FMA, swizzled conflict-free
//                smem tile, 2 blocks/SM (4 warps/SMSP), software-pipelined
//                row loads. Output tile 4d x 8h x 128w, 8 w/thread.
// ---------------------------------------------------------------------------

#define NB 8
typedef unsigned long long ull;

__device__ float g_zc[NB * 512];
__device__ float g_zn[NB];
__device__ float g_t1[(size_t)NB * 128 * 121 * 121];
__device__ float g_t2[(size_t)NB * 128 * 121 * 121];
__device__ float g_dinv[(size_t)NB * 121 * 121 * 121];

// ---------------- packed f32x2 helpers ----------------
__device__ __forceinline__ void fma2(ull& a, ull x, ull z) {
    asm("fma.rn.f32x2 %0, %1, %2, %0;" : "+l"(a) : "l"(x), "l"(z));
}
__device__ __forceinline__ float2 u2f(ull u) {
    float2 f;
    asm("mov.b64 {%0, %1}, %2;" : "=f"(f.x), "=f"(f.y) : "l"(u));
    return f;
}

// ---------------- template stats ----------------
__global__ void ncc_k_template(const float* __restrict__ z) {
    __shared__ float red[512];
    int b = blockIdx.x, t = threadIdx.x;
    float v = z[b * 512 + t];
    red[t] = v;
    __syncthreads();
    for (int s = 256; s > 0; s >>= 1) {
        if (t < s) red[t] += red[t + s];
        __syncthreads();
    }
    float mean = red[0] * (1.0f / 512.0f);
    __syncthreads();
    float c = v - mean;
    g_zc[b * 512 + t] = c;
    red[t] = c * c;
    __syncthreads();
    for (int s = 256; s > 0; s >>= 1) {
        if (t < s) red[t] += red[t + s];
        __syncthreads();
    }
    if (t == 0) g_zn[b] = sqrtf(red[0]);
}

// ---------------- fused W + H window sums (one (b,d) slice per block) -------
#define WH_SMEM (3 * 16384 * 4)
__global__ void __launch_bounds__(256) ncc_k_whsum(const float* __restrict__ x) {
    extern __shared__ float sm[];
    float* xs = sm;              // [128][128]
    float* s1 = sm + 16384;      // [128][128] (w<121 valid)
    float* s2 = sm + 32768;
    int bd = blockIdx.x, tid = threadIdx.x;
    const float* xp = x + (size_t)bd * 16384;
    for (int i = tid; i < 16384; i += 256) xs[i] = xp[i];
    __syncthreads();
    for (int i = tid; i < 16384; i += 256) {
        int w = i & 127;
        if (w < 121) {
            float a = 0.f, c = 0.f;
#pragma unroll
            for (int k = 0; k < 8; k++) {
                float v = xs[i + k];
                a += v;
                c += v * v;
            }
            s1[i] = a;
            s2[i] = c;
        }
    }
    __syncthreads();
    for (int i = tid; i < 121 * 128; i += 256) {
        int ho = i >> 7, w = i & 127;
        if (w < 121) {
            float a = 0.f, c = 0.f;
#pragma unroll
            for (int k = 0; k < 8; k++) {
                a += s1[i + (k << 7)];
                c += s2[i + (k << 7)];
            }
            size_t o = ((size_t)bd * 121 + ho) * 121 + w;
            g_t1[o] = a;
            g_t2[o] = c;
        }
    }
}

// ---------------- rolling D sums + denominator inverse ----------------------
__global__ void __launch_bounds__(256) ncc_k_dsum2() {
    int p = blockIdx.x * 256 + threadIdx.x;
    if (p >= 14641) return;
    int h = p / 121, w = p - h * 121;
    int b = blockIdx.z;
    const int dst[5] = {0, 31, 61, 91, 121};
    int d0 = dst[blockIdx.y], d1 = dst[blockIdx.y + 1];
    size_t tbase = (((size_t)(b * 128)) * 121 + h) * 121 + w;
    float r1[8], r2[8], s1 = 0.f, s2 = 0.f;
#pragma unroll
    for (int k = 0; k < 8; k++) {
        float a = g_t1[tbase + (size_t)(d0 + k) * 14641];
        float c = g_t2[tbase + (size_t)(d0 + k) * 14641];
        r1[k] = a;
        r2[k] = c;
        s1 += a;
        s2 += c;
    }
    float zn = g_zn[b];
    size_t obase = (((size_t)(b * 121)) * 121 + h) * 121 + w;
    for (int dd = d0; dd < d1; dd += 8) {
#pragma unroll
        for (int j = 0; j < 8; j++) {
            int d = dd + j;
            if (d < d1) {
                float var = fmaxf(s2 - s1 * s1 * (1.0f / 512.0f), 0.0f);
                g_dinv[obase + (size_t)d * 14641] =
                    1.0f / (sqrtf(var + 1e-12f) * zn + 1e-5f);
                if (d + 1 < d1) {
                    float n1 = g_t1[tbase + (size_t)(d + 8) * 14641];
                    float n2 = g_t2[tbase + (size_t)(d + 8) * 14641];
                    s1 += n1 - r1[j];
                    r1[j] = n1;
                    s2 += n2 - r2[j];
                    r2[j] = n2;
                }
            }
        }
    }
}

// ---------------- cross-correlation (FMA-bound) -----------------------------
// Block 256 threads = 8 warps, 2 blocks/SM. Output tile: 4(d) x 8(h) x 128(w).
// Thread: od = c>>2 (0..3), oh0 = (c&3)*2 (phases 0/1), wt = tid&15, 8 w each.
// Accumulators per phase: even bank A[4] (out pairs 2p,2p+1), odd bank B[5]
// (out pairs 2i-1,2i). Software pipeline: tile row r+1 and z row r+1 are
// issued before phase0's FMAs; phase1 of iter r uses tile row r+1 + z row r.
// Tile rows swizzled by 16B granule: phys = g ^ (g>>3) (involution),
// row stride 152 floats (38 granules, == 6 mod 8) -> conflict-free LDS.128.
#define CTD 11
#define CTHH 15
#define RST 152
#define TILE_F (CTD * CTHH * RST)            // 25,080 floats
#define CR_SMEM ((TILE_F + 1024) * 4)        // +512 z ull pairs = 104,416 B

__device__ __forceinline__ void cr_loadrow(ull* pe, const float* rp,
                                           const int* off) {
#pragma unroll
    for (int q = 0; q < 4; q++) {
        ulonglong2 v = *(const ulonglong2*)(rp + off[q]);
        pe[2 * q] = v.x;
        pe[2 * q + 1] = v.y;
    }
}
__device__ __forceinline__ void cr_loadz(ull* zr, const ull* zrow) {
    const ulonglong2* z2 = (const ulonglong2*)zrow;
    ulonglong2 a = z2[0], b = z2[1], c = z2[2], d = z2[3];
    zr[0] = a.x; zr[1] = a.y; zr[2] = b.x; zr[3] = b.y;
    zr[4] = c.x; zr[5] = c.y; zr[6] = d.x; zr[7] = d.y;
}
__device__ __forceinline__ void cr_fma(ull* A, ull* B, const ull* pe,
                                       const ull* zr) {
#pragma unroll
    for (int m = 0; m < 4; m++) {
        ull ze = zr[2 * m];
#pragma unroll
        for (int p = 0; p < 4; p++) fma2(A[p], pe[p + m], ze);
    }
#pragma unroll
    for (int m = 0; m < 4; m++) {
        ull zo = zr[2 * m + 1];
#pragma unroll
        for (int i = 0; i < 5; i++) fma2(B[i], pe[i + m], zo);
    }
}

__global__ void __launch_bounds__(256, 2) ncc_k_cross(const float* __restrict__ x,
                                                      float* __restrict__ out) {
    extern __shared__ float sm[];
    float* tile = sm;
    ull* zp = (ull*)(sm + TILE_F);

    int b = blockIdx.z;
    int d0 = blockIdx.x * 4, h0 = blockIdx.y * 8;
    int tid = threadIdx.x;

    const float* xb = x + (size_t)b * 2097152;
    for (int i = tid; i < TILE_F; i += 256) {
        int row = i / RST;
        int wp = i - row * RST;
        int lg = wp >> 2;
        lg = lg ^ (lg >> 3);                 // involution
        int w = (lg << 2) | (wp & 3);
        float v = 0.f;
        if (w < 128) {
            int dd = row / CTHH, hh = row - dd * CTHH;
            int gd = min(d0 + dd, 127), gh = min(h0 + hh, 127);
            v = xb[((size_t)(gd * 128 + gh)) * 128 + w];
        }
        tile[i] = v;
    }
    for (int t = tid; t < 512; t += 256) {
        float zv = g_zc[b * 512 + t];
        float2 f = make_float2(zv, zv);
        zp[t] = *(ull*)&f;
    }
    __syncthreads();

    int wt = tid & 15, c = tid >> 4;
    int od = c >> 2, oh0 = (c & 3) * 2;
    int wb = wt * 8;

    int off[4];
#pragma unroll
    for (int q = 0; q < 4; q++) {
        int g = 2 * wt + q;
        off[q] = (g ^ (g >> 3)) << 2;        // swizzled float offset
    }

    ull A0[4], B0[5], A1[4], B1[5];
#pragma unroll
    for (int p = 0; p < 4; p++) { A0[p] = 0ull; A1[p] = 0ull; }
#pragma unroll
    for (int i = 0; i < 5; i++) { B0[i] = 0ull; B1[i] = 0ull; }

#pragma unroll 1
    for (int kd = 0; kd < 8; kd++) {
        const float* bp = tile + (od + kd) * (CTHH * RST) + oh0 * RST;
        const ull* zkd = zp + (kd << 6);     // kd*64

        ull peb[2][8], zb[2][8];
        cr_loadrow(peb[0], bp, off);
        cr_loadz(zb[0], zkd);

#pragma unroll
        for (int r = 0; r < 8; r++) {
            cr_loadrow(peb[(r + 1) & 1], bp + (r + 1) * RST, off);
            if (r < 7) cr_loadz(zb[(r + 1) & 1], zkd + (r + 1) * 8);
            // phase0: output row oh0, tile row r, z row r
            cr_fma(A0, B0, peb[r & 1], zb[r & 1]);
            // phase1: output row oh0+1, tile row r+1, z row r
            cr_fma(A1, B1, peb[(r + 1) & 1], zb[r & 1]);
        }
    }

    int d = d0 + od;
    if (d >= 121) return;
    size_t dbase_o = ((size_t)(b * 121 + d)) * 121;

    {
        int h = h0 + oh0;
        if (h < 121) {
            float res[8];
#pragma unroll
            for (int p = 0; p < 4; p++) {
                float2 a = u2f(A0[p]);
                float2 bl = u2f(B0[p]);
                float2 br = u2f(B0[p + 1]);
                res[2 * p] = a.x + bl.y;
                res[2 * p + 1] = a.y + br.x;
            }
            size_t base = (dbase_o + h) * 121;
#pragma unroll
            for (int j = 0; j < 8; j++) {
                int w = wb + j;
                if (w < 121) out[base + w] = res[j] * __ldg(&g_dinv[base + w]);
            }
        }
    }
    {
        int h = h0 + oh0 + 1;
        if (h < 121) {
            float res[8];
#pragma unroll
            for (int p = 0; p < 4; p++) {
                float2 a = u2f(A1[p]);
                float2 bl = u2f(B1[p]);
                float2 br = u2f(B1[p + 1]);
                res[2 * p] = a.x + bl.y;
                res[2 * p + 1] = a.y + br.x;
            }
            size_t base = (dbase_o + h) * 121;
#pragma unroll
            for (int j = 0; j < 8; j++) {
                int w = wb + j;
                if (w < 121) out[base + w] = res[j] * __ldg(&g_dinv[base + w]);
            }
        }
    }
}

// ---------------------------------------------------------------------------
extern "C" void kernel_launch(void* const* d_in, const int* in_sizes, int n_in,
                              void* d_out, int out_size) {
    (void)n_in;
    (void)out_size;
    const float* z = (const float*)d_in[0];
    const float* x = (const float*)d_in[1];
    if (in_sizes[0] != NB * 512) {
        z = (const float*)d_in[1];
        x = (const float*)d_in[0];
    }
    float* out = (float*)d_out;

    cudaFuncSetAttribute(ncc_k_whsum,
                         cudaFuncAttributeMaxDynamicSharedMemorySize, WH_SMEM);
    cudaFuncSetAttribute(ncc_k_cross,
                         cudaFuncAttributeMaxDynamicSharedMemorySize, CR_SMEM);

    ncc_k_template<<<NB, 512>>>(z);
    ncc_k_whsum<<<NB * 128, 256, WH_SMEM>>>(x);
    ncc_k_dsum2<<<dim3(58, 4, NB), 256>>>();
    ncc_k_cross<<<dim3(31, 16, NB), 256, CR_SMEM>>>(x, out);
}

// round 10
// speedup vs baseline: 1.4148x; 1.2840x over previous
#include <cuda_runtime.h>
#include <math.h>

// ---------------------------------------------------------------------------
// NCC3D: z[8,1,8,8,8], x[8,1,128,128,128] -> out[8,1,121,121,121]
//   k_template : zero-mean template + L2 norm
//   k_whsum    : fused W+H window sums of x, x^2 (smem-resident per (b,d) slice)
//   k_dsum2    : rolling D window sums + denominator inverse -> g_dinv
//   k_cross    : direct correlation, f32x2 packed FMA, swizzled conflict-free
//                smem tile, 2 blocks/SM, vectorized prologue, z kept plain in
//                smem (half the z LDS) and duplicated on the fly.
// ---------------------------------------------------------------------------

#define NB 8
typedef unsigned long long ull;

__device__ float g_zc[NB * 512];
__device__ float g_zn[NB];
__device__ float g_t1[(size_t)NB * 128 * 121 * 121];
__device__ float g_t2[(size_t)NB * 128 * 121 * 121];
__device__ float g_dinv[(size_t)NB * 121 * 121 * 121];

// ---------------- packed f32x2 helpers ----------------
__device__ __forceinline__ void fma2(ull& a, ull x, ull z) {
    asm("fma.rn.f32x2 %0, %1, %2, %0;" : "+l"(a) : "l"(x), "l"(z));
}
__device__ __forceinline__ float2 u2f(ull u) {
    float2 f;
    asm("mov.b64 {%0, %1}, %2;" : "=f"(f.x), "=f"(f.y) : "l"(u));
    return f;
}
__device__ __forceinline__ ull dupf(float f) {
    ull r;
    asm("mov.b64 %0, {%1, %1};" : "=l"(r) : "f"(f));
    return r;
}

// ---------------- template stats ----------------
__global__ void ncc_k_template(const float* __restrict__ z) {
    __shared__ float red[512];
    int b = blockIdx.x, t = threadIdx.x;
    float v = z[b * 512 + t];
    red[t] = v;
    __syncthreads();
    for (int s = 256; s > 0; s >>= 1) {
        if (t < s) red[t] += red[t + s];
        __syncthreads();
    }
    float mean = red[0] * (1.0f / 512.0f);
    __syncthreads();
    float c = v - mean;
    g_zc[b * 512 + t] = c;
    red[t] = c * c;
    __syncthreads();
    for (int s = 256; s > 0; s >>= 1) {
        if (t < s) red[t] += red[t + s];
        __syncthreads();
    }
    if (t == 0) g_zn[b] = sqrtf(red[0]);
}

// ---------------- fused W + H window sums (one (b,d) slice per block) -------
#define WH_SMEM (3 * 16384 * 4)
__global__ void __launch_bounds__(256) ncc_k_whsum(const float* __restrict__ x) {
    extern __shared__ float sm[];
    float* xs = sm;              // [128][128]
    float* s1 = sm + 16384;      // [128][128] (w<121 valid)
    float* s2 = sm + 32768;
    int bd = blockIdx.x, tid = threadIdx.x;
    const float* xp = x + (size_t)bd * 16384;
    for (int i = tid; i < 16384; i += 256) xs[i] = xp[i];
    __syncthreads();
    for (int i = tid; i < 16384; i += 256) {
        int w = i & 127;
        if (w < 121) {
            float a = 0.f, c = 0.f;
#pragma unroll
            for (int k = 0; k < 8; k++) {
                float v = xs[i + k];
                a += v;
                c += v * v;
            }
            s1[i] = a;
            s2[i] = c;
        }
    }
    __syncthreads();
    for (int i = tid; i < 121 * 128; i += 256) {
        int ho = i >> 7, w = i & 127;
        if (w < 121) {
            float a = 0.f, c = 0.f;
#pragma unroll
            for (int k = 0; k < 8; k++) {
                a += s1[i + (k << 7)];
                c += s2[i + (k << 7)];
            }
            size_t o = ((size_t)bd * 121 + ho) * 121 + w;
            g_t1[o] = a;
            g_t2[o] = c;
        }
    }
}

// ---------------- rolling D sums + denominator inverse ----------------------
__global__ void __launch_bounds__(256) ncc_k_dsum2() {
    int p = blockIdx.x * 256 + threadIdx.x;
    if (p >= 14641) return;
    int h = p / 121, w = p - h * 121;
    int b = blockIdx.z;
    const int dst[5] = {0, 31, 61, 91, 121};
    int d0 = dst[blockIdx.y], d1 = dst[blockIdx.y + 1];
    size_t tbase = (((size_t)(b * 128)) * 121 + h) * 121 + w;
    float r1[8], r2[8], s1 = 0.f, s2 = 0.f;
#pragma unroll
    for (int k = 0; k < 8; k++) {
        float a = g_t1[tbase + (size_t)(d0 + k) * 14641];
        float c = g_t2[tbase + (size_t)(d0 + k) * 14641];
        r1[k] = a;
        r2[k] = c;
        s1 += a;
        s2 += c;
    }
    float zn = g_zn[b];
    size_t obase = (((size_t)(b * 121)) * 121 + h) * 121 + w;
    for (int dd = d0; dd < d1; dd += 8) {
#pragma unroll
        for (int j = 0; j < 8; j++) {
            int d = dd + j;
            if (d < d1) {
                float var = fmaxf(s2 - s1 * s1 * (1.0f / 512.0f), 0.0f);
                g_dinv[obase + (size_t)d * 14641] =
                    1.0f / (sqrtf(var + 1e-12f) * zn + 1e-5f);
                if (d + 1 < d1) {
                    float n1 = g_t1[tbase + (size_t)(d + 8) * 14641];
                    float n2 = g_t2[tbase + (size_t)(d + 8) * 14641];
                    s1 += n1 - r1[j];
                    r1[j] = n1;
                    s2 += n2 - r2[j];
                    r2[j] = n2;
                }
            }
        }
    }
}

// ---------------- cross-correlation (FMA-bound) -----------------------------
// Block 256 threads = 8 warps, 2 blocks/SM. Output tile: 4(d) x 8(h) x 128(w).
// Thread: od = c>>2 (0..3), oh0 = (c&3)*2 (phases 0/1), wt = tid&15, 8 w each.
// Accumulators per phase: even bank A[4] (out pairs 2p,2p+1), odd bank B[5]
// (out pairs 2i-1,2i). Tile row r+1 prefetched before phase0 FMAs; phase1 of
// iter r uses tile row r+1 + z row r. z stored PLAIN in smem (512 floats);
// loaded per 2-row chunk (4 LDS.128) and lane-duplicated with mov.b64.
// Tile rows swizzled by 16B granule: phys = g ^ (g>>3),
// row stride 152 floats (38 granules, == 6 mod 8) -> conflict-free LDS.128.
#define CTD 11
#define CTHH 15
#define RST 152
#define TILE_F (CTD * CTHH * RST)            // 25,080 floats
#define CR_SMEM ((TILE_F + 512) * 4)         // + 512 plain z floats

__device__ __forceinline__ void cr_loadrow(ull* pe, const float* rp,
                                           const int* off) {
#pragma unroll
    for (int q = 0; q < 4; q++) {
        ulonglong2 v = *(const ulonglong2*)(rp + off[q]);
        pe[2 * q] = v.x;
        pe[2 * q + 1] = v.y;
    }
}
__device__ __forceinline__ void cr_fma(ull* A, ull* B, const ull* pe,
                                       const ull* zr) {
#pragma unroll
    for (int m = 0; m < 4; m++) {
        ull ze = zr[2 * m];
#pragma unroll
        for (int p = 0; p < 4; p++) fma2(A[p], pe[p + m], ze);
    }
#pragma unroll
    for (int m = 0; m < 4; m++) {
        ull zo = zr[2 * m + 1];
#pragma unroll
        for (int i = 0; i < 5; i++) fma2(B[i], pe[i + m], zo);
    }
}

__global__ void __launch_bounds__(256, 2) ncc_k_cross(const float* __restrict__ x,
                                                      float* __restrict__ out) {
    extern __shared__ float sm[];
    float* tile = sm;
    float* zs = sm + TILE_F;                 // plain z floats [512]

    int b = blockIdx.z;
    int d0 = blockIdx.x * 4, h0 = blockIdx.y * 8;
    int tid = threadIdx.x;

    // ---- vectorized prologue: 165 rows x 32 data granules, LDG.128/STS.128
    const float* xb = x + (size_t)b * 2097152;
    for (int i = tid; i < 165 * 32; i += 256) {
        int row = i >> 5;
        int g = i & 31;
        int phys = g ^ (g >> 3);
        int dd = row / CTHH, hh = row - dd * CTHH;
        int gd = min(d0 + dd, 127), gh = min(h0 + hh, 127);
        float4 v = *(const float4*)(xb + ((size_t)(gd * 128 + gh) << 7) + (g << 2));
        *(float4*)(tile + row * RST + (phys << 2)) = v;
    }
    // zero pad granules: logical 32,33 -> phys 36,37
    for (int i = tid; i < 165 * 2; i += 256) {
        int row = i >> 1;
        int phys = 36 + (i & 1);
        *(float4*)(tile + row * RST + (phys << 2)) = make_float4(0.f, 0.f, 0.f, 0.f);
    }
    for (int t = tid; t < 512; t += 256) zs[t] = g_zc[b * 512 + t];
    __syncthreads();

    int wt = tid & 15, c = tid >> 4;
    int od = c >> 2, oh0 = (c & 3) * 2;
    int wb = wt * 8;

    int off[4];
#pragma unroll
    for (int q = 0; q < 4; q++) {
        int g = 2 * wt + q;
        off[q] = (g ^ (g >> 3)) << 2;        // swizzled float offset
    }

    ull A0[4], B0[5], A1[4], B1[5];
#pragma unroll
    for (int p = 0; p < 4; p++) { A0[p] = 0ull; A1[p] = 0ull; }
#pragma unroll
    for (int i = 0; i < 5; i++) { B0[i] = 0ull; B1[i] = 0ull; }

#pragma unroll 1
    for (int kd = 0; kd < 8; kd++) {
        const float* bp = tile + (od + kd) * (CTHH * RST) + oh0 * RST;
        const float* zk = zs + (kd << 6);    // 64 plain z floats for this kd

        ull peb[2][8];
        cr_loadrow(peb[0], bp, off);

#pragma unroll
        for (int rh = 0; rh < 4; rh++) {
            // z chunk: rows 2rh, 2rh+1 (16 floats, 4 LDS.128 broadcast)
            float zc[16];
#pragma unroll
            for (int q = 0; q < 4; q++) {
                float4 v = *(const float4*)(zk + (rh << 4) + (q << 2));
                zc[4 * q] = v.x; zc[4 * q + 1] = v.y;
                zc[4 * q + 2] = v.z; zc[4 * q + 3] = v.w;
            }
#pragma unroll
            for (int rr = 0; rr < 2; rr++) {
                int r = rh * 2 + rr;
                ull zd[8];
#pragma unroll
                for (int j = 0; j < 8; j++) zd[j] = dupf(zc[rr * 8 + j]);
                cr_loadrow(peb[(r + 1) & 1], bp + (r + 1) * RST, off);
                // phase0: output row oh0,   tile row r,   z row r
                cr_fma(A0, B0, peb[r & 1], zd);
                // phase1: output row oh0+1, tile row r+1, z row r
                cr_fma(A1, B1, peb[(r + 1) & 1], zd);
            }
        }
    }

    int d = d0 + od;
    if (d >= 121) return;
    size_t dbase_o = ((size_t)(b * 121 + d)) * 121;

    {
        int h = h0 + oh0;
        if (h < 121) {
            float res[8];
#pragma unroll
            for (int p = 0; p < 4; p++) {
                float2 a = u2f(A0[p]);
                float2 bl = u2f(B0[p]);
                float2 br = u2f(B0[p + 1]);
                res[2 * p] = a.x + bl.y;
                res[2 * p + 1] = a.y + br.x;
            }
            size_t base = (dbase_o + h) * 121;
#pragma unroll
            for (int j = 0; j < 8; j++) {
                int w = wb + j;
                if (w < 121) out[base + w] = res[j] * __ldg(&g_dinv[base + w]);
            }
        }
    }
    {
        int h = h0 + oh0 + 1;
        if (h < 121) {
            float res[8];
#pragma unroll
            for (int p = 0; p < 4; p++) {
                float2 a = u2f(A1[p]);
                float2 bl = u2f(B1[p]);
                float2 br = u2f(B1[p + 1]);
                res[2 * p] = a.x + bl.y;
                res[2 * p + 1] = a.y + br.x;
            }
            size_t base = (dbase_o + h) * 121;
#pragma unroll
            for (int j = 0; j < 8; j++) {
                int w = wb + j;
                if (w < 121) out[base + w] = res[j] * __ldg(&g_dinv[base + w]);
            }
        }
    }
}

// ---------------------------------------------------------------------------
extern "C" void kernel_launch(void* const* d_in, const int* in_sizes, int n_in,
                              void* d_out, int out_size) {
    (void)n_in;
    (void)out_size;
    const float* z = (const float*)d_in[0];
    const float* x = (const float*)d_in[1];
    if (in_sizes[0] != NB * 512) {
        z = (const float*)d_in[1];
        x = (const float*)d_in[0];
    }
    float* out = (float*)d_out;

    cudaFuncSetAttribute(ncc_k_whsum,
                         cudaFuncAttributeMaxDynamicSharedMemorySize, WH_SMEM);
    cudaFuncSetAttribute(ncc_k_cross,
                         cudaFuncAttributeMaxDynamicSharedMemorySize, CR_SMEM);

    ncc_k_template<<<NB, 512>>>(z);
    ncc_k_whsum<<<NB * 128, 256, WH_SMEM>>>(x);
    ncc_k_dsum2<<<dim3(58, 4, NB), 256>>>();
    ncc_k_cross<<<dim3(31, 16, NB), 256, CR_SMEM>>>(x, out);
}

// round 11
// speedup vs baseline: 1.5152x; 1.0710x over previous
#include <cuda_runtime.h>
#include <math.h>

// ---------------------------------------------------------------------------
// NCC3D: z[8,1,8,8,8], x[8,1,128,128,128] -> out[8,1,121,121,121]
//   k_template : zero-mean template + L2 norm
//   k_whsum2   : W+H window sums, half-slice blocks (70KB smem, 3 blocks/SM),
//                rolling-register W pass straight from gmem (no xs staging)
//   k_dsum2    : rolling D window sums + denominator inverse -> g_dinv
//   k_cross    : direct correlation, f32x2 packed FMA, swizzled conflict-free
//                smem tile, 2 blocks/SM, vectorized prologue, plain z in smem,
//                double-buffered z chunks (latency hidden).
// ---------------------------------------------------------------------------

#define NB 8
typedef unsigned long long ull;

__device__ float g_zc[NB * 512];
__device__ float g_zn[NB];
__device__ float g_t1[(size_t)NB * 128 * 121 * 121];
__device__ float g_t2[(size_t)NB * 128 * 121 * 121];
__device__ float g_dinv[(size_t)NB * 121 * 121 * 121];

// ---------------- packed f32x2 helpers ----------------
__device__ __forceinline__ void fma2(ull& a, ull x, ull z) {
    asm("fma.rn.f32x2 %0, %1, %2, %0;" : "+l"(a) : "l"(x), "l"(z));
}
__device__ __forceinline__ float2 u2f(ull u) {
    float2 f;
    asm("mov.b64 {%0, %1}, %2;" : "=f"(f.x), "=f"(f.y) : "l"(u));
    return f;
}
__device__ __forceinline__ ull dupf(float f) {
    ull r;
    asm("mov.b64 %0, {%1, %1};" : "=l"(r) : "f"(f));
    return r;
}

// ---------------- template stats ----------------
__global__ void ncc_k_template(const float* __restrict__ z) {
    __shared__ float red[512];
    int b = blockIdx.x, t = threadIdx.x;
    float v = z[b * 512 + t];
    red[t] = v;
    __syncthreads();
    for (int s = 256; s > 0; s >>= 1) {
        if (t < s) red[t] += red[t + s];
        __syncthreads();
    }
    float mean = red[0] * (1.0f / 512.0f);
    __syncthreads();
    float c = v - mean;
    g_zc[b * 512 + t] = c;
    red[t] = c * c;
    __syncthreads();
    for (int s = 256; s > 0; s >>= 1) {
        if (t < s) red[t] += red[t + s];
        __syncthreads();
    }
    if (t == 0) g_zn[b] = sqrtf(red[0]);
}

// ---------------- W + H window sums, half-slice (3 blocks/SM) ---------------
// Block = (half, bd). half0: x rows 0..70, outputs ho 0..63.
//                     half1: x rows 64..127, outputs ho 64..120.
// W pass: tasks (row, seg). seg<3: 10 LDG.128 -> 32 rolling outputs;
//         seg==3: 8 LDG.128 -> 25 outputs. Results into smem ss1/ss2 [71][124].
// H pass: 8-row sums of ss -> g_t1/g_t2, coalesced stores.
#define SS_PITCH 124
#define WH2_SMEM (2 * 71 * SS_PITCH * 4)

template <int NLD, int NOUT>
__device__ __forceinline__ void wpass_seg(const float* __restrict__ xrow,
                                          float* o1, float* o2) {
    float f[NLD * 4];
#pragma unroll
    for (int k = 0; k < NLD; k++) {
        float4 v = *(const float4*)(xrow + 4 * k);
        f[4 * k] = v.x; f[4 * k + 1] = v.y;
        f[4 * k + 2] = v.z; f[4 * k + 3] = v.w;
    }
    float a = 0.f, c = 0.f;
#pragma unroll
    for (int j = 0; j < 8; j++) { a += f[j]; c += f[j] * f[j]; }
    o1[0] = a; o2[0] = c;
#pragma unroll
    for (int j = 1; j < NOUT; j++) {
        float nv = f[j + 7], ov = f[j - 1];
        a += nv - ov;
        c += nv * nv - ov * ov;
        o1[j] = a; o2[j] = c;
    }
}

__global__ void __launch_bounds__(256, 3) ncc_k_whsum2(const float* __restrict__ x) {
    extern __shared__ float sm[];
    float* ss1 = sm;
    float* ss2 = sm + 71 * SS_PITCH;

    int half = blockIdx.x;
    int bd = blockIdx.y;
    int tid = threadIdx.x;
    int row0 = half * 64;
    int nrows = half ? 64 : 71;
    int nho = half ? 57 : 64;
    const float* xs = x + (size_t)bd * 16384;

    for (int t = tid; t < nrows * 4; t += 256) {
        int r = t >> 2, seg = t & 3;
        const float* xrow = xs + (row0 + r) * 128 + seg * 32;
        float* o1 = ss1 + r * SS_PITCH + seg * 32;
        float* o2 = ss2 + r * SS_PITCH + seg * 32;
        if (seg < 3) wpass_seg<10, 32>(xrow, o1, o2);
        else         wpass_seg<8, 25>(xrow, o1, o2);
    }
    __syncthreads();

    for (int i = tid; i < nho * 128; i += 256) {
        int ho = i >> 7, w = i & 127;
        if (w < 121) {
            float a = 0.f, c = 0.f;
#pragma unroll
            for (int k = 0; k < 8; k++) {
                a += ss1[(ho + k) * SS_PITCH + w];
                c += ss2[(ho + k) * SS_PITCH + w];
            }
            size_t o = ((size_t)bd * 121 + row0 + ho) * 121 + w;
            g_t1[o] = a;
            g_t2[o] = c;
        }
    }
}

// ---------------- rolling D sums + denominator inverse ----------------------
__global__ void __launch_bounds__(256) ncc_k_dsum2() {
    int p = blockIdx.x * 256 + threadIdx.x;
    if (p >= 14641) return;
    int h = p / 121, w = p - h * 121;
    int b = blockIdx.z;
    const int dst[5] = {0, 31, 61, 91, 121};
    int d0 = dst[blockIdx.y], d1 = dst[blockIdx.y + 1];
    size_t tbase = (((size_t)(b * 128)) * 121 + h) * 121 + w;
    float r1[8], r2[8], s1 = 0.f, s2 = 0.f;
#pragma unroll
    for (int k = 0; k < 8; k++) {
        float a = g_t1[tbase + (size_t)(d0 + k) * 14641];
        float c = g_t2[tbase + (size_t)(d0 + k) * 14641];
        r1[k] = a;
        r2[k] = c;
        s1 += a;
        s2 += c;
    }
    float zn = g_zn[b];
    size_t obase = (((size_t)(b * 121)) * 121 + h) * 121 + w;
    for (int dd = d0; dd < d1; dd += 8) {
#pragma unroll
        for (int j = 0; j < 8; j++) {
            int d = dd + j;
            if (d < d1) {
                float var = fmaxf(s2 - s1 * s1 * (1.0f / 512.0f), 0.0f);
                g_dinv[obase + (size_t)d * 14641] =
                    1.0f / (sqrtf(var + 1e-12f) * zn + 1e-5f);
                if (d + 1 < d1) {
                    float n1 = g_t1[tbase + (size_t)(d + 8) * 14641];
                    float n2 = g_t2[tbase + (size_t)(d + 8) * 14641];
                    s1 += n1 - r1[j];
                    r1[j] = n1;
                    s2 += n2 - r2[j];
                    r2[j] = n2;
                }
            }
        }
    }
}

// ---------------- cross-correlation (FMA-bound) -----------------------------
// Block 256 threads = 8 warps, 2 blocks/SM. Output tile: 4(d) x 8(h) x 128(w).
// Thread: od = c>>2 (0..3), oh0 = (c&3)*2 (phases 0/1), wt = tid&15, 8 w each.
// Accumulators per phase: even bank A[4] (out pairs 2p,2p+1), odd bank B[5]
// (out pairs 2i-1,2i). Tile row r+1 prefetched before phase0 FMAs; phase1 of
// iter r uses tile row r+1 + z row r. z stored PLAIN in smem; z chunks
// double-buffered (prefetch rh+1 before rh FMAs) -> no exposed LDS latency.
// Tile rows swizzled by 16B granule: phys = g ^ (g>>3),
// row stride 152 floats (38 granules, == 6 mod 8) -> conflict-free LDS.128.
#define CTD 11
#define CTHH 15
#define RST 152
#define TILE_F (CTD * CTHH * RST)            // 25,080 floats
#define CR_SMEM ((TILE_F + 512) * 4)         // + 512 plain z floats

__device__ __forceinline__ void cr_loadrow(ull* pe, const float* rp,
                                           const int* off) {
#pragma unroll
    for (int q = 0; q < 4; q++) {
        ulonglong2 v = *(const ulonglong2*)(rp + off[q]);
        pe[2 * q] = v.x;
        pe[2 * q + 1] = v.y;
    }
}
__device__ __forceinline__ void cr_loadz(float* zc, const float* zk) {
#pragma unroll
    for (int q = 0; q < 4; q++) {
        float4 v = *(const float4*)(zk + (q << 2));
        zc[4 * q] = v.x; zc[4 * q + 1] = v.y;
        zc[4 * q + 2] = v.z; zc[4 * q + 3] = v.w;
    }
}
__device__ __forceinline__ void cr_fma(ull* A, ull* B, const ull* pe,
                                       const ull* zr) {
#pragma unroll
    for (int m = 0; m < 4; m++) {
        ull ze = zr[2 * m];
#pragma unroll
        for (int p = 0; p < 4; p++) fma2(A[p], pe[p + m], ze);
    }
#pragma unroll
    for (int m = 0; m < 4; m++) {
        ull zo = zr[2 * m + 1];
#pragma unroll
        for (int i = 0; i < 5; i++) fma2(B[i], pe[i + m], zo);
    }
}

__global__ void __launch_bounds__(256, 2) ncc_k_cross(const float* __restrict__ x,
                                                      float* __restrict__ out) {
    extern __shared__ float sm[];
    float* tile = sm;
    float* zs = sm + TILE_F;                 // plain z floats [512]

    int b = blockIdx.z;
    int d0 = blockIdx.x * 4, h0 = blockIdx.y * 8;
    int tid = threadIdx.x;

    // ---- vectorized prologue: 165 rows x 32 data granules, LDG.128/STS.128
    const float* xb = x + (size_t)b * 2097152;
    for (int i = tid; i < 165 * 32; i += 256) {
        int row = i >> 5;
        int g = i & 31;
        int phys = g ^ (g >> 3);
        int dd = row / CTHH, hh = row - dd * CTHH;
        int gd = min(d0 + dd, 127), gh = min(h0 + hh, 127);
        float4 v = *(const float4*)(xb + ((size_t)(gd * 128 + gh) << 7) + (g << 2));
        *(float4*)(tile + row * RST + (phys << 2)) = v;
    }
    // zero pad granules: logical 32,33 -> phys 36,37
    for (int i = tid; i < 165 * 2; i += 256) {
        int row = i >> 1;
        int phys = 36 + (i & 1);
        *(float4*)(tile + row * RST + (phys << 2)) = make_float4(0.f, 0.f, 0.f, 0.f);
    }
    for (int t = tid; t < 512; t += 256) zs[t] = g_zc[b * 512 + t];
    __syncthreads();

    int wt = tid & 15, c = tid >> 4;
    int od = c >> 2, oh0 = (c & 3) * 2;
    int wb = wt * 8;

    int off[4];
#pragma unroll
    for (int q = 0; q < 4; q++) {
        int g = 2 * wt + q;
        off[q] = (g ^ (g >> 3)) << 2;        // swizzled float offset
    }

    ull A0[4], B0[5], A1[4], B1[5];
#pragma unroll
    for (int p = 0; p < 4; p++) { A0[p] = 0ull; A1[p] = 0ull; }
#pragma unroll
    for (int i = 0; i < 5; i++) { B0[i] = 0ull; B1[i] = 0ull; }

#pragma unroll 1
    for (int kd = 0; kd < 8; kd++) {
        const float* bp = tile + (od + kd) * (CTHH * RST) + oh0 * RST;
        const float* zk = zs + (kd << 6);    // 64 plain z floats for this kd

        ull peb[2][8];
        cr_loadrow(peb[0], bp, off);

        float zcb[2][16];                    // double-buffered z chunks
        cr_loadz(zcb[0], zk);

#pragma unroll
        for (int rh = 0; rh < 4; rh++) {
            if (rh < 3) cr_loadz(zcb[(rh + 1) & 1], zk + ((rh + 1) << 4));
            const float* zc = zcb[rh & 1];
#pragma unroll
            for (int rr = 0; rr < 2; rr++) {
                int r = rh * 2 + rr;
                ull zd[8];
#pragma unroll
                for (int j = 0; j < 8; j++) zd[j] = dupf(zc[rr * 8 + j]);
                cr_loadrow(peb[(r + 1) & 1], bp + (r + 1) * RST, off);
                // phase0: output row oh0,   tile row r,   z row r
                cr_fma(A0, B0, peb[r & 1], zd);
                // phase1: output row oh0+1, tile row r+1, z row r
                cr_fma(A1, B1, peb[(r + 1) & 1], zd);
            }
        }
    }

    int d = d0 + od;
    if (d >= 121) return;
    size_t dbase_o = ((size_t)(b * 121 + d)) * 121;

    {
        int h = h0 + oh0;
        if (h < 121) {
            float res[8];
#pragma unroll
            for (int p = 0; p < 4; p++) {
                float2 a = u2f(A0[p]);
                float2 bl = u2f(B0[p]);
                float2 br = u2f(B0[p + 1]);
                res[2 * p] = a.x + bl.y;
                res[2 * p + 1] = a.y + br.x;
            }
            size_t base = (dbase_o + h) * 121;
#pragma unroll
            for (int j = 0; j < 8; j++) {
                int w = wb + j;
                if (w < 121) out[base + w] = res[j] * __ldg(&g_dinv[base + w]);
            }
        }
    }
    {
        int h = h0 + oh0 + 1;
        if (h < 121) {
            float res[8];
#pragma unroll
            for (int p = 0; p < 4; p++) {
                float2 a = u2f(A1[p]);
                float2 bl = u2f(B1[p]);
                float2 br = u2f(B1[p + 1]);
                res[2 * p] = a.x + bl.y;
                res[2 * p + 1] = a.y + br.x;
            }
            size_t base = (dbase_o + h) * 121;
#pragma unroll
            for (int j = 0; j < 8; j++) {
                int w = wb + j;
                if (w < 121) out[base + w] = res[j] * __ldg(&g_dinv[base + w]);
            }
        }
    }
}

// ---------------------------------------------------------------------------
extern "C" void kernel_launch(void* const* d_in, const int* in_sizes, int n_in,
                              void* d_out, int out_size) {
    (void)n_in;
    (void)out_size;
    const float* z = (const float*)d_in[0];
    const float* x = (const float*)d_in[1];
    if (in_sizes[0] != NB * 512) {
        z = (const float*)d_in[1];
        x = (const float*)d_in[0];
    }
    float* out = (float*)d_out;

    cudaFuncSetAttribute(ncc_k_whsum2,
                         cudaFuncAttributeMaxDynamicSharedMemorySize, WH2_SMEM);
    cudaFuncSetAttribute(ncc_k_cross,
                         cudaFuncAttributeMaxDynamicSharedMemorySize, CR_SMEM);

    ncc_k_template<<<NB, 512>>>(z);
    ncc_k_whsum2<<<dim3(2, NB * 128), 256, WH2_SMEM>>>(x);
    ncc_k_dsum2<<<dim3(58, 4, NB), 256>>>();
    ncc_k_cross<<<dim3(31, 16, NB), 256, CR_SMEM>>>(x, out);
}